// round 15
// baseline (speedup 1.0000x reference)
#include <cuda_runtime.h>
#include <cuda_fp16.h>

// AdderNet 2D (K=3,S=1,P=1): out[n,f,y,x] = -sum_{c,i,j} |W[f,c,i,j] - xpad[n,c,y+i,x+j]|
// x: [8,64,32,32] f32, W: [64,64,3,3] f32, out: [8,64,32,32] f32.
//
// Two-phase. Prep: x -> padded fp16 [n][c][34][34]; W -> negated fp16 tiles
// [fg][k][f]. Main: fp16 HADD2 core (abs folded), 512 CTAs (RT=2, FG=16),
// 256 thr, launch_bounds(256,4) -> 4 CTAs/SM, capacity 592 >= 512 = ONE WAVE.

#define CIN   64
#define NFILT 64
#define HW    32
#define NIMG  8

#define FG    16
#define RT    2
#define XROWS (RT + 2)          // 4
#define XCOLS 34
#define PHW   34

#define SX_ELEMS (CIN * XROWS * XCOLS)   // 8704 halves = 17408 B
#define SW_ELEMS (CIN * 9 * FG)          // 9216 halves = 18432 B
#define SMEM_BYTES ((SX_ELEMS + SW_ELEMS) * 2)   // 35840 B ; sR (12KB) aliases sX

#define QX_ELEMS (NIMG * CIN * PHW * PHW)  // 591872
#define QW_ELEMS (4 * CIN * 9 * FG)        // 36864
#define PREP_TOTAL (QX_ELEMS + QW_ELEMS)

__device__ __half g_qX[QX_ELEMS];          // [n][c][ph][pw], zero border
__device__ __half g_qW[QW_ELEMS];          // [fg][k][f], NEGATED

__global__ __launch_bounds__(256, 8)
void prep_kernel(const float* __restrict__ x, const float* __restrict__ W)
{
    int idx = blockIdx.x * 256 + threadIdx.x;
    if (idx < QX_ELEMS) {
        int pw = idx % PHW;
        int t  = idx / PHW;
        int ph = t % PHW;
        int nc = t / PHW;
        float v = 0.0f;
        if (ph >= 1 && ph < 33 && pw >= 1 && pw < 33)
            v = x[(size_t)nc * (HW * HW) + (ph - 1) * HW + (pw - 1)];
        g_qX[idx] = __float2half_rn(v);
    } else if (idx < PREP_TOTAL) {
        int wi = idx - QX_ELEMS;
        int f  = wi & 15;
        int k  = (wi >> 4) % (CIN * 9);
        int fg = wi / (16 * CIN * 9);
        g_qW[wi] = __float2half_rn(-W[(size_t)(fg * FG + f) * (CIN * 9) + k]);
    }
}

__global__ __launch_bounds__(256, 4)
void adder2d_kernel(float* __restrict__ out)
{
    extern __shared__ __half smemh[];
    __half* sX = smemh;                       // [c][r 0..3][col 0..33] fp16
    __half* sW = smemh + SX_ELEMS;            // [k][ff 0..15] fp16, NEGATED
    float*  sR = (float*)smemh;               // aliases after main loop: [3][16][64]

    const int tid = threadIdx.x;              // 0..255
    const int qtr = tid >> 6;                 // channel quarter 0..3 (16 ch each)
    const int wk  = tid & 63;                 // worker = one output position
    const int yw  = wk >> 5;                  // 0..1
    const int col = wk & 31;
    const int fg  = blockIdx.x;               // 0..3
    const int rt  = blockIdx.y;               // 0..15
    const int n   = blockIdx.z;               // 0..7
    const int y0  = rt * RT;
    const int f0  = fg * FG;

    // ---- x slab: straight uint copies from padded g_qX (rows contiguous) ----
    {
        const unsigned* srcx = (const unsigned*)g_qX
                             + (size_t)n * CIN * (PHW * PHW / 2) + y0 * (PHW / 2);
        unsigned* dstx = (unsigned*)sX;
        for (int idx = tid; idx < CIN * (XROWS * XCOLS / 2); idx += 256) {
            int c   = idx / (XROWS * XCOLS / 2);          // /68
            int off = idx - c * (XROWS * XCOLS / 2);
            dstx[idx] = srcx[c * (PHW * PHW / 2) + off];
        }
    }
    // ---- weight tile: pure uint4 memcpy ----
    {
        const uint4* srcw = (const uint4*)(g_qW + fg * SW_ELEMS);
        uint4* dstw = (uint4*)sW;
        for (int idx = tid; idx < SW_ELEMS / 8; idx += 256)
            dstw[idx] = srcw[idx];
    }
    __syncthreads();

    float facc[16];
#pragma unroll
    for (int p = 0; p < 16; p++) facc[p] = 0.0f;

    const int cbeg = qtr * (CIN / 4);
    const __half* xrow = sX + cbeg * (XROWS * XCOLS) + yw * XCOLS + col;
    const __half* wch  = sW + cbeg * 9 * FG;

#pragma unroll 1
    for (int cp = 0; cp < 8; cp++) {           // 8 pairs of channels per quarter
        __half2 hacc[8];
#pragma unroll
        for (int t = 0; t < 8; t++) hacc[t] = __float2half2_rn(0.0f);

#pragma unroll
        for (int cc = 0; cc < 2; cc++) {       // 2 channels per promote (18 taps)
#pragma unroll
            for (int i = 0; i < 3; i++) {
                __half2 xa[3];
#pragma unroll
                for (int j = 0; j < 3; j++)
                    xa[j] = __half2half2(xrow[i * XCOLS + j]);
#pragma unroll
                for (int j = 0; j < 3; j++) {
                    const uint4 rA = *(const uint4*)(wch + (i * 3 + j) * FG);     // f 0..7
                    const uint4 rB = *(const uint4*)(wch + (i * 3 + j) * FG + 8); // f 8..15
                    const __half2* wa = (const __half2*)&rA;
                    const __half2* wb = (const __half2*)&rB;
#pragma unroll
                    for (int q = 0; q < 4; q++) {
                        __half2 d;
                        d = __hadd2(xa[j], wa[q]); hacc[q]     = __hadd2(hacc[q],     __habs2(d));
                        d = __hadd2(xa[j], wb[q]); hacc[4 + q] = __hadd2(hacc[4 + q], __habs2(d));
                    }
                }
            }
            xrow += XROWS * XCOLS;
            wch  += 9 * FG;
        }
#pragma unroll
        for (int t = 0; t < 8; t++) {
            float2 f = __half22float2(hacc[t]);
            facc[2 * t]     += f.x;
            facc[2 * t + 1] += f.y;
        }
    }

    // ---- combine 4 channel quarters (sR aliases sX, now dead) ----
    __syncthreads();
    if (qtr != 0) {
        float* buf = sR + (size_t)(qtr - 1) * (16 * 64);
#pragma unroll
        for (int p = 0; p < 16; p++) buf[p * 64 + wk] = facc[p];   // conflict-free
    }
    __syncthreads();

    if (qtr == 0) {
#pragma unroll
        for (int p = 0; p < 16; p++) {
            float s = facc[p];
#pragma unroll
            for (int r = 0; r < 3; r++)
                s += sR[(size_t)r * (16 * 64) + p * 64 + wk];
            facc[p] = s;
        }
        // ---- write: t = g*4 + q ; filter = g*8 + 2q + lane ----
        const int gy = y0 + yw;
#pragma unroll
        for (int t = 0; t < 8; t++) {
            int g = t >> 2;
            int q = t & 3;
            int f = g * 8 + q * 2;
            float* outp = out + (((size_t)n * NFILT + f0 + f) * HW + gy) * HW + col;
            outp[0]       = -facc[2 * t];
            outp[HW * HW] = -facc[2 * t + 1];
        }
    }
}

extern "C" void kernel_launch(void* const* d_in, const int* in_sizes, int n_in,
                              void* d_out, int out_size)
{
    const float* x = (const float*)d_in[0];
    const float* W = (const float*)d_in[1];
    if (n_in >= 2 && in_sizes[0] == NFILT * CIN * 9 && in_sizes[1] == NIMG * CIN * HW * HW) {
        const float* t = x; x = W; W = t;
    }
    float* out = (float*)d_out;

    prep_kernel<<<(PREP_TOTAL + 255) / 256, 256>>>(x, W);

    dim3 grid(NFILT / FG, HW / RT, NIMG);   // 4 x 16 x 8 = 512 CTAs, ONE wave @4/SM
    adder2d_kernel<<<grid, 256, SMEM_BYTES>>>(out);
}

// round 16
// speedup vs baseline: 1.0393x; 1.0393x over previous
#include <cuda_runtime.h>
#include <cuda_fp16.h>

// AdderNet 2D (K=3,S=1,P=1): out[n,f,y,x] = -sum_{c,i,j} |W[f,c,i,j] - xpad[n,c,y+i,x+j]|
// x: [8,64,32,32] f32, W: [64,64,3,3] f32, out: [8,64,32,32] f32.
//
// Two-phase. Prep (row-vectorized): x -> padded fp16 [n][c][34][34]; W ->
// negated fp16 tiles [fg][k][f]. Main: R14 config (256 CTAs, RT=4, 512 thr,
// 2 CTAs/SM, fp16 HADD2 core with folded abs), promote fp16->fp32 every 4 ch.

#define CIN   64
#define NFILT 64
#define HW    32
#define NIMG  8

#define FG    16
#define RT    4
#define XROWS (RT + 2)          // 6
#define XCOLS 34
#define PHW   34

#define SX_ELEMS (CIN * XROWS * XCOLS)   // 13056 halves = 26112 B
#define SW_ELEMS (CIN * 9 * FG)          // 9216 halves  = 18432 B
#define SMEM_BYTES ((SX_ELEMS + SW_ELEMS) * 2)   // 44544 B ; sR (24KB) aliases sX

#define QX_ELEMS (NIMG * CIN * PHW * PHW)  // 591872
#define QX_ROWS  (NIMG * CIN * PHW)        // 17408
#define QW_ELEMS (4 * CIN * 9 * FG)        // 36864
#define PREP_THREADS (QX_ROWS + QW_ELEMS)  // 54272

__device__ __half g_qX[QX_ELEMS];          // [n][c][ph][pw], zero border
__device__ __half g_qW[QW_ELEMS];          // [fg][k][f], NEGATED

__device__ __forceinline__ unsigned h2bits(__half a, __half b) {
    __half2 p = __halves2half2(a, b);
    return *(unsigned*)&p;
}

__global__ __launch_bounds__(256, 8)
void prep_kernel(const float* __restrict__ x, const float* __restrict__ W)
{
    int idx = blockIdx.x * 256 + threadIdx.x;
    if (idx < QX_ROWS) {
        // one thread = one padded row (34 halves = 17 aligned uints)
        int nc = idx / PHW;
        int ph = idx - nc * PHW;
        unsigned* dst = (unsigned*)(g_qX + (size_t)idx * PHW);
        if (ph == 0 || ph == PHW - 1) {
#pragma unroll
            for (int k = 0; k < 17; k++) dst[k] = 0u;
        } else {
            const float4* src = (const float4*)(x + (size_t)nc * (HW * HW) + (ph - 1) * HW);
            __half h[32];
#pragma unroll
            for (int k = 0; k < 8; k++) {
                float4 v = src[k];
                h[4 * k + 0] = __float2half_rn(v.x);
                h[4 * k + 1] = __float2half_rn(v.y);
                h[4 * k + 2] = __float2half_rn(v.z);
                h[4 * k + 3] = __float2half_rn(v.w);
            }
            const __half hz = __ushort_as_half(0);
            dst[0] = h2bits(hz, h[0]);
#pragma unroll
            for (int k = 1; k < 16; k++)
                dst[k] = h2bits(h[2 * k - 1], h[2 * k]);
            dst[16] = h2bits(h[31], hz);
        }
    } else if (idx < PREP_THREADS) {
        int wi = idx - QX_ROWS;
        int f  = wi & 15;
        int k  = (wi >> 4) % (CIN * 9);
        int fg = wi / (16 * CIN * 9);
        g_qW[wi] = __float2half_rn(-W[(size_t)(fg * FG + f) * (CIN * 9) + k]);
    }
}

__global__ __launch_bounds__(512, 2)
void adder2d_kernel(float* __restrict__ out)
{
    extern __shared__ __half smemh[];
    __half* sX = smemh;                       // [c][r 0..5][col 0..33] fp16
    __half* sW = smemh + SX_ELEMS;            // [k][ff 0..15] fp16, NEGATED
    float*  sR = (float*)smemh;               // aliases after main loop: [3][16][128]

    const int tid = threadIdx.x;
    const int qtr = tid >> 7;                 // channel quarter 0..3
    const int wk  = tid & 127;                // worker = one output position
    const int yw  = wk >> 5;                  // 0..3
    const int col = wk & 31;
    const int fg  = blockIdx.x;               // 0..3
    const int rt  = blockIdx.y;               // 0..7
    const int n   = blockIdx.z;               // 0..7
    const int y0  = rt * RT;
    const int f0  = fg * FG;

    // ---- x slab: straight uint copies from padded g_qX (rows contiguous) ----
    {
        const unsigned* srcx = (const unsigned*)g_qX
                             + (size_t)n * CIN * (PHW * PHW / 2) + y0 * (PHW / 2);
        unsigned* dstx = (unsigned*)sX;
        for (int idx = tid; idx < CIN * (XROWS * XCOLS / 2); idx += 512) {
            int c   = idx / (XROWS * XCOLS / 2);          // /102
            int off = idx - c * (XROWS * XCOLS / 2);
            dstx[idx] = srcx[c * (PHW * PHW / 2) + off];
        }
    }
    // ---- weight tile: pure uint4 memcpy ----
    {
        const uint4* srcw = (const uint4*)(g_qW + fg * SW_ELEMS);
        uint4* dstw = (uint4*)sW;
        for (int idx = tid; idx < SW_ELEMS / 8; idx += 512)
            dstw[idx] = srcw[idx];
    }
    __syncthreads();

    float facc[16];
#pragma unroll
    for (int p = 0; p < 16; p++) facc[p] = 0.0f;

    const int cbeg = qtr * (CIN / 4);
    const __half* xrow = sX + cbeg * (XROWS * XCOLS) + yw * XCOLS + col;
    const __half* wch  = sW + cbeg * 9 * FG;

#pragma unroll 1
    for (int cp = 0; cp < 4; cp++) {           // 4 blocks of 4 channels
        __half2 hacc[8];
#pragma unroll
        for (int t = 0; t < 8; t++) hacc[t] = __float2half2_rn(0.0f);

#pragma unroll
        for (int cc = 0; cc < 4; cc++) {       // 4 channels per promote (36 taps)
#pragma unroll
            for (int i = 0; i < 3; i++) {
                __half2 xa[3];
#pragma unroll
                for (int j = 0; j < 3; j++)
                    xa[j] = __half2half2(xrow[i * XCOLS + j]);
#pragma unroll
                for (int j = 0; j < 3; j++) {
                    const uint4 rA = *(const uint4*)(wch + (i * 3 + j) * FG);     // f 0..7
                    const uint4 rB = *(const uint4*)(wch + (i * 3 + j) * FG + 8); // f 8..15
                    const __half2* wa = (const __half2*)&rA;
                    const __half2* wb = (const __half2*)&rB;
#pragma unroll
                    for (int q = 0; q < 4; q++) {
                        __half2 d;
                        d = __hadd2(xa[j], wa[q]); hacc[q]     = __hadd2(hacc[q],     __habs2(d));
                        d = __hadd2(xa[j], wb[q]); hacc[4 + q] = __hadd2(hacc[4 + q], __habs2(d));
                    }
                }
            }
            xrow += XROWS * XCOLS;
            wch  += 9 * FG;
        }
        // ---- promote fp16 partials (36 taps, |sum| <~ 60 ok) into fp32 ----
#pragma unroll
        for (int t = 0; t < 8; t++) {
            float2 f = __half22float2(hacc[t]);
            facc[2 * t]     += f.x;
            facc[2 * t + 1] += f.y;
        }
    }

    // ---- combine 4 channel quarters (sR aliases sX, now dead) ----
    __syncthreads();
    if (qtr != 0) {
        float* buf = sR + (size_t)(qtr - 1) * (16 * 128);
#pragma unroll
        for (int p = 0; p < 16; p++) buf[p * 128 + wk] = facc[p];  // conflict-free
    }
    __syncthreads();

    if (qtr == 0) {
#pragma unroll
        for (int p = 0; p < 16; p++) {
            float s = facc[p];
#pragma unroll
            for (int r = 0; r < 3; r++)
                s += sR[(size_t)r * (16 * 128) + p * 128 + wk];
            facc[p] = s;
        }
        // ---- write: t = g*4 + q ; filter = g*8 + 2q + lane ----
        const int gy = y0 + yw;
#pragma unroll
        for (int t = 0; t < 8; t++) {
            int g = t >> 2;
            int q = t & 3;
            int f = g * 8 + q * 2;
            float* outp = out + (((size_t)n * NFILT + f0 + f) * HW + gy) * HW + col;
            outp[0]       = -facc[2 * t];
            outp[HW * HW] = -facc[2 * t + 1];
        }
    }
}

extern "C" void kernel_launch(void* const* d_in, const int* in_sizes, int n_in,
                              void* d_out, int out_size)
{
    const float* x = (const float*)d_in[0];
    const float* W = (const float*)d_in[1];
    if (n_in >= 2 && in_sizes[0] == NFILT * CIN * 9 && in_sizes[1] == NIMG * CIN * HW * HW) {
        const float* t = x; x = W; W = t;
    }
    float* out = (float*)d_out;

    static int smem_set = -1;
    if (smem_set < 0) {
        cudaFuncSetAttribute(adder2d_kernel,
                             cudaFuncAttributeMaxDynamicSharedMemorySize, SMEM_BYTES);
        smem_set = 1;
    }

    prep_kernel<<<(PREP_THREADS + 255) / 256, 256>>>(x, W);

    dim3 grid(NFILT / FG, HW / RT, NIMG);   // 4 x 8 x 8 = 256 CTAs, 2 per SM
    adder2d_kernel<<<grid, 512, SMEM_BYTES>>>(out);
}

// round 17
// speedup vs baseline: 1.0611x; 1.0210x over previous
#include <cuda_runtime.h>
#include <cuda_fp16.h>

// AdderNet 2D (K=3,S=1,P=1): out[n,f,y,x] = -sum_{c,i,j} |W[f,c,i,j] - xpad[n,c,y+i,x+j]|
// x: [8,64,32,32] f32, W: [64,64,3,3] f32, out: [8,64,32,32] f32.
//
// SINGLE kernel (no prep launch tax). Row-vectorized in-CTA prologue:
// x slab loaded one smem-row per thread (8x LDG.128 -> 16 cvt -> 17 STS.32),
// weights with divide-free index mapping. fp16 HADD2 core (abs folded),
// 256 CTAs (RT=4, FG=16), 512 thr, 2 CTAs/SM, promote fp16->fp32 every 4 ch.

#define CIN   64
#define NFILT 64
#define HW    32
#define NIMG  8

#define FG    16
#define RT    4
#define XROWS (RT + 2)          // 6
#define XCOLS 34

#define SX_ELEMS (CIN * XROWS * XCOLS)   // 13056 halves = 26112 B
#define SW_ELEMS (CIN * 9 * FG)          // 9216 halves  = 18432 B
#define SMEM_BYTES ((SX_ELEMS + SW_ELEMS) * 2)   // 44544 B ; sR (24KB) aliases sX

__device__ __forceinline__ unsigned h2bits(__half a, __half b) {
    __half2 p = __halves2half2(a, b);
    return *(unsigned*)&p;
}

__global__ __launch_bounds__(512, 2)
void adder2d_kernel(const float* __restrict__ x,
                    const float* __restrict__ W,
                    float* __restrict__ out)
{
    extern __shared__ __half smemh[];
    __half* sX = smemh;                       // [c][r 0..5][col 0..33] fp16, zero pad
    __half* sW = smemh + SX_ELEMS;            // [k][ff 0..15] fp16, NEGATED
    float*  sR = (float*)smemh;               // aliases after main loop: [3][16][128]

    const int tid = threadIdx.x;
    const int qtr = tid >> 7;                 // channel quarter 0..3
    const int wk  = tid & 127;                // worker = one output position
    const int yw  = wk >> 5;                  // 0..3
    const int col = wk & 31;
    const int fg  = blockIdx.x;               // 0..3
    const int rt  = blockIdx.y;               // 0..7
    const int n   = blockIdx.z;               // 0..7
    const int y0  = rt * RT;
    const int f0  = fg * FG;

    // ---- x slab: one thread per smem row (384 rows of 34 halves = 17 uints) ----
    if (tid < CIN * XROWS) {
        const int c  = tid / XROWS;
        const int r  = tid - c * XROWS;
        const int gr = y0 - 1 + r;            // global row
        unsigned* dst = (unsigned*)(sX + tid * XCOLS);
        if ((unsigned)gr >= HW) {
#pragma unroll
            for (int k = 0; k < 17; k++) dst[k] = 0u;
        } else {
            const float4* src = (const float4*)
                (x + ((size_t)n * CIN + c) * (HW * HW) + gr * HW);
            __half h[32];
#pragma unroll
            for (int k = 0; k < 8; k++) {
                float4 v = src[k];
                h[4 * k + 0] = __float2half_rn(v.x);
                h[4 * k + 1] = __float2half_rn(v.y);
                h[4 * k + 2] = __float2half_rn(v.z);
                h[4 * k + 3] = __float2half_rn(v.w);
            }
            const __half hz = __ushort_as_half(0);
            dst[0] = h2bits(hz, h[0]);
#pragma unroll
            for (int k = 1; k < 16; k++)
                dst[k] = h2bits(h[2 * k - 1], h[2 * k]);
            dst[16] = h2bits(h[31], hz);
        }
    }
    // ---- weights, divide-free: sW[idx] = -W[(f0 + (idx&15))*576 + (idx>>4)] ----
#pragma unroll
    for (int it = 0; it < SW_ELEMS / 512; it++) {
        int idx = it * 512 + tid;
        int f   = idx & 15;
        int k   = idx >> 4;
        sW[idx] = __float2half_rn(-W[(size_t)(f0 + f) * (CIN * 9) + k]);
    }
    __syncthreads();

    float facc[16];
#pragma unroll
    for (int p = 0; p < 16; p++) facc[p] = 0.0f;

    const int cbeg = qtr * (CIN / 4);
    const __half* xrow = sX + cbeg * (XROWS * XCOLS) + yw * XCOLS + col;
    const __half* wch  = sW + cbeg * 9 * FG;

#pragma unroll 1
    for (int cp = 0; cp < 4; cp++) {           // 4 blocks of 4 channels
        __half2 hacc[8];
#pragma unroll
        for (int t = 0; t < 8; t++) hacc[t] = __float2half2_rn(0.0f);

#pragma unroll
        for (int cc = 0; cc < 4; cc++) {       // 4 channels per promote (36 taps)
#pragma unroll
            for (int i = 0; i < 3; i++) {
                __half2 xa[3];
#pragma unroll
                for (int j = 0; j < 3; j++)
                    xa[j] = __half2half2(xrow[i * XCOLS + j]);
#pragma unroll
                for (int j = 0; j < 3; j++) {
                    const uint4 rA = *(const uint4*)(wch + (i * 3 + j) * FG);     // f 0..7
                    const uint4 rB = *(const uint4*)(wch + (i * 3 + j) * FG + 8); // f 8..15
                    const __half2* wa = (const __half2*)&rA;
                    const __half2* wb = (const __half2*)&rB;
#pragma unroll
                    for (int q = 0; q < 4; q++) {
                        __half2 d;
                        d = __hadd2(xa[j], wa[q]); hacc[q]     = __hadd2(hacc[q],     __habs2(d));
                        d = __hadd2(xa[j], wb[q]); hacc[4 + q] = __hadd2(hacc[4 + q], __habs2(d));
                    }
                }
            }
            xrow += XROWS * XCOLS;
            wch  += 9 * FG;
        }
        // ---- promote fp16 partials (36 taps) into fp32 ----
#pragma unroll
        for (int t = 0; t < 8; t++) {
            float2 f = __half22float2(hacc[t]);
            facc[2 * t]     += f.x;
            facc[2 * t + 1] += f.y;
        }
    }

    // ---- combine 4 channel quarters (sR aliases sX, now dead) ----
    __syncthreads();
    if (qtr != 0) {
        float* buf = sR + (size_t)(qtr - 1) * (16 * 128);
#pragma unroll
        for (int p = 0; p < 16; p++) buf[p * 128 + wk] = facc[p];  // conflict-free
    }
    __syncthreads();

    if (qtr == 0) {
#pragma unroll
        for (int p = 0; p < 16; p++) {
            float s = facc[p];
#pragma unroll
            for (int r = 0; r < 3; r++)
                s += sR[(size_t)r * (16 * 128) + p * 128 + wk];
            facc[p] = s;
        }
        // ---- write: t = g*4 + q ; filter = g*8 + 2q + lane ----
        const int gy = y0 + yw;
#pragma unroll
        for (int t = 0; t < 8; t++) {
            int g = t >> 2;
            int q = t & 3;
            int f = g * 8 + q * 2;
            float* outp = out + (((size_t)n * NFILT + f0 + f) * HW + gy) * HW + col;
            outp[0]       = -facc[2 * t];
            outp[HW * HW] = -facc[2 * t + 1];
        }
    }
}

extern "C" void kernel_launch(void* const* d_in, const int* in_sizes, int n_in,
                              void* d_out, int out_size)
{
    const float* x = (const float*)d_in[0];
    const float* W = (const float*)d_in[1];
    if (n_in >= 2 && in_sizes[0] == NFILT * CIN * 9 && in_sizes[1] == NIMG * CIN * HW * HW) {
        const float* t = x; x = W; W = t;
    }
    float* out = (float*)d_out;

    static int smem_set = -1;
    if (smem_set < 0) {
        cudaFuncSetAttribute(adder2d_kernel,
                             cudaFuncAttributeMaxDynamicSharedMemorySize, SMEM_BYTES);
        smem_set = 1;
    }

    dim3 grid(NFILT / FG, HW / RT, NIMG);   // 4 x 8 x 8 = 256 CTAs, 2 per SM
    adder2d_kernel<<<grid, 512, SMEM_BYTES>>>(x, W, out);
}